// round 17
// baseline (speedup 1.0000x reference)
#include <cuda_runtime.h>
#include <cuda_bf16.h>
#include <math.h>

// Problem constants
#define B_  64
#define T_  512
#define I_  512
#define H_  1024
#define G4  4096           // 4*H
#define BH  (B_*H_)        // 65536
#define NCTA 128
#define BK  32
#define NSTAGE (H_/BK)     // 32
#define NTHR 512

typedef unsigned long long u64;
typedef unsigned int u32;

// ---------------------------------------------------------------------------
// Device scratch
// ---------------------------------------------------------------------------
__device__ float g_xp[(size_t)2 * T_ * B_ * G4];   // xp[dir][t][b][g]  (1 GiB)
__device__ float g_wT[2][H_][G4];                  // w_hh transposed [dir][k][n] (32 MB)
__device__ float g_hT[2][2][H_][B_];               // h: [phase][dir][j][b]
__device__ unsigned g_bar_count;
__device__ volatile unsigned g_bar_sense;

// ---------------------------------------------------------------------------
// PTX helpers
// ---------------------------------------------------------------------------
__device__ __forceinline__ void fma2(u64& c, u64 a, u64 b) {
    asm volatile("fma.rn.f32x2 %0, %1, %2, %0;" : "+l"(c) : "l"(a), "l"(b));
}
__device__ __forceinline__ u64 rep2(float x) {
    u64 r;
    asm volatile("mov.b64 %0, {%1, %1};" : "=l"(r) : "f"(x));
    return r;
}
__device__ __forceinline__ void cp_async16(u32 smem_addr, const void* gptr) {
    asm volatile("cp.async.cg.shared.global [%0], [%1], 16;" :: "r"(smem_addr), "l"(gptr));
}
__device__ __forceinline__ void cp_commit() { asm volatile("cp.async.commit_group;"); }
__device__ __forceinline__ void cp_wait1()  { asm volatile("cp.async.wait_group 1;"); }
__device__ __forceinline__ void cp_wait0()  { asm volatile("cp.async.wait_group 0;"); }
__device__ __forceinline__ float lo32(u64 v) { return __uint_as_float((u32)(v & 0xffffffffull)); }
__device__ __forceinline__ float hi32(u64 v) { return __uint_as_float((u32)(v >> 32)); }

// ---------------------------------------------------------------------------
// Init (every replay): zero h(phase 0) and barrier state
// ---------------------------------------------------------------------------
__global__ void init_state_kernel() {
    int i = blockIdx.x * blockDim.x + threadIdx.x;
    if (i < 2 * BH) ((float*)g_hT)[i] = 0.0f;
    if (i == 0) { g_bar_count = 0; g_bar_sense = 0; }
}

// ---------------------------------------------------------------------------
// Transpose w_hh [4096,1024] -> g_wT [dir][1024][4096]
// ---------------------------------------------------------------------------
__global__ void __launch_bounds__(256) transpose_w_kernel(
    const float* __restrict__ wfw, const float* __restrict__ wbw)
{
    __shared__ float tile[32][33];
    const int dir = blockIdx.z;
    const float* w = dir ? wbw : wfw;
    const int n0 = blockIdx.x * 32;
    const int k0 = blockIdx.y * 32;
    const int tx = threadIdx.x & 31, ty = threadIdx.x >> 5;
#pragma unroll
    for (int r = 0; r < 32; r += 8)
        tile[ty + r][tx] = w[(size_t)(n0 + ty + r) * H_ + k0 + tx];
    __syncthreads();
#pragma unroll
    for (int r = 0; r < 32; r += 8)
        g_wT[dir][k0 + ty + r][n0 + tx] = tile[tx][ty + r];
}

// ---------------------------------------------------------------------------
// Input projection (R2 version — known good)
// ---------------------------------------------------------------------------
__global__ void __launch_bounds__(128) input_proj_kernel(
    const float* __restrict__ x,
    const float* __restrict__ w_fw, const float* __restrict__ w_bw,
    const float* __restrict__ bi_fw, const float* __restrict__ bh_fw,
    const float* __restrict__ bi_bw, const float* __restrict__ bh_bw)
{
    const int gt  = blockIdx.x;
    const int t   = blockIdx.y;
    const int dir = blockIdx.z;

    const float* w     = dir ? w_bw : w_fw;
    const float* bi    = dir ? bi_bw : bi_fw;
    const float* bh    = dir ? bh_bw : bh_fw;
    const int    src_t = dir ? (T_ - 1 - t) : t;

    __shared__ float sA[16][68];
    __shared__ float sB[16][68];

    const int tid = threadIdx.x;
    const int tr  = tid >> 4;
    const int tc  = tid & 15;

    u64 acc[4][4];
#pragma unroll
    for (int p = 0; p < 4; p++)
#pragma unroll
        for (int j = 0; j < 4; j++) acc[p][j] = 0ull;

    const float* Abase = x + (size_t)src_t * I_;
    const float* Bbase = w + (size_t)(gt * 64) * I_;

    for (int k0 = 0; k0 < I_; k0 += 16) {
#pragma unroll 4
        for (int idx = tid; idx < 1024; idx += 128) {
            int kk = idx & 15, m = idx >> 4;
            sA[kk][m] = Abase[(size_t)m * (T_ * I_) + k0 + kk];
        }
#pragma unroll 4
        for (int idx = tid; idx < 1024; idx += 128) {
            int kk = idx & 15, n = idx >> 4;
            sB[kk][n] = Bbase[(size_t)n * I_ + k0 + kk];
        }
        __syncthreads();
#pragma unroll
        for (int kk = 0; kk < 16; kk++) {
            const float* ap = &sA[kk][tr * 8];
            u64 a0 = *(const u64*)(ap + 0);
            u64 a1 = *(const u64*)(ap + 2);
            u64 a2 = *(const u64*)(ap + 4);
            u64 a3 = *(const u64*)(ap + 6);
            float4 b4 = *(const float4*)&sB[kk][tc * 4];
            u64 b0 = rep2(b4.x), b1 = rep2(b4.y), b2 = rep2(b4.z), b3 = rep2(b4.w);
            fma2(acc[0][0], a0, b0); fma2(acc[0][1], a0, b1); fma2(acc[0][2], a0, b2); fma2(acc[0][3], a0, b3);
            fma2(acc[1][0], a1, b0); fma2(acc[1][1], a1, b1); fma2(acc[1][2], a1, b2); fma2(acc[1][3], a1, b3);
            fma2(acc[2][0], a2, b0); fma2(acc[2][1], a2, b1); fma2(acc[2][2], a2, b2); fma2(acc[2][3], a2, b3);
            fma2(acc[3][0], a3, b0); fma2(acc[3][1], a3, b1); fma2(acc[3][2], a3, b2); fma2(acc[3][3], a3, b3);
        }
        __syncthreads();
    }

    const int gbase = gt * 64 + tc * 4;
    float bias[4];
#pragma unroll
    for (int j = 0; j < 4; j++) bias[j] = bi[gbase + j] + bh[gbase + j];

    float* outp = g_xp + (((size_t)dir * T_ + t) * B_) * G4;
#pragma unroll
    for (int i = 0; i < 8; i++) {
        int m = tr * 8 + i;
        int p = i >> 1;
        float v0 = (i & 1) ? hi32(acc[p][0]) : lo32(acc[p][0]);
        float v1 = (i & 1) ? hi32(acc[p][1]) : lo32(acc[p][1]);
        float v2 = (i & 1) ? hi32(acc[p][2]) : lo32(acc[p][2]);
        float v3 = (i & 1) ? hi32(acc[p][3]) : lo32(acc[p][3]);
        float4 v = make_float4(v0 + bias[0], v1 + bias[1], v2 + bias[2], v3 + bias[3]);
        *(float4*)(outp + (size_t)m * G4 + gbase) = v;
    }
}

// ---------------------------------------------------------------------------
// Persistent LSTM recurrence, split-K x8 with 8x8 microtile.
// grid=128 (dir,jt per CTA), block=512 (16 warps; 8 K-groups of 64 threads).
// Group g: kk in [4g, 4g+4) of every stage; thread (tr,tc) owns rows tr*8..+7,
// cols tc*8..+7 (64 cells, acc 32 u64). Per thread-kk: A 32B + B 32B = 64 B
// for 64 MACs -> 1.0 B/MAC (R16 was 1.5) -> crossbar ~= fma floor (balanced).
// Staging/ring/syncs identical to R16. Partials: 8 sG regions, stride 68.
// xp loads + cell indices moved to epilogue to cut loop register pressure.
// ---------------------------------------------------------------------------
#define SA_FLOATS (3 * BK * 64)    // 6144
#define SB_FLOATS (3 * BK * 64)    // 6144
#define SG_STRIDE 68               // 16B-aligned rows
#define SG_REGION (64 * SG_STRIDE) // 4352 floats per group region
#define SMEM_BYTES (8 * SG_REGION * 4)   // 139264 B (ring 49152 aliases inside)

__global__ void __launch_bounds__(NTHR, 1) lstm_persistent_kernel(float* __restrict__ out)
{
    extern __shared__ __align__(16) float smem[];
    float* sA = smem;
    float* sB = smem + SA_FLOATS;
    float* sG = smem;                        // 8 regions of 4352 floats

    const int bx  = blockIdx.x;
    const int dir = bx & 1;
    const int jt  = bx >> 1;                 // 0..63

    const int tid = threadIdx.x;
    const int g   = tid >> 6;                // K-group 0..7 (64 thr each)
    const int loc = tid & 63;
    const int tr  = loc >> 3;                // 0..7 -> rows tr*8..+7
    const int tc  = loc & 7;                 // 0..7 -> cols tc*8..+7

    const float* wT = &g_wT[dir][0][0];
    const u32 sA_u = (u32)__cvta_generic_to_shared(sA);
    const u32 sB_u = (u32)__cvta_generic_to_shared(sB);

    // staging assignment (identical to R16)
    const int b_kk = tid >> 4;
    const int b_pc = tid & 15;
    const int pc_q = b_pc >> 2, pc_s = b_pc & 3;
    const size_t bcol_off = (size_t)(pc_q * H_ + jt * 16 + pc_s * 4);
    const u32 b_sm_off = (u32)((b_kk * 256) + (pc_q * 16 + pc_s * 4) * 4);

    float creg[2] = {0.0f, 0.0f};

    for (int t = 0; t < T_; t++) {
        const int phase = t & 1;
        const float* hT  = &g_hT[phase][dir][0][0];
        float*       hTn = &g_hT[phase ^ 1][dir][0][0];

        u64 acc[4][8];
#pragma unroll
        for (int p = 0; p < 4; p++)
#pragma unroll
            for (int c = 0; c < 8; c++) acc[p][c] = 0ull;

#define ISSUE(s) do {                                                             \
            const int _s = (s);                                                   \
            const int _buf = _s % 3;                                              \
            const u32 _ad = sA_u + (u32)(_buf * BK * 64 * 4);                     \
            const u32 _bd = sB_u + (u32)(_buf * BK * 64 * 4);                     \
            cp_async16(_ad + (u32)tid * 16, hT + (size_t)_s * 2048 + tid * 4);    \
            cp_async16(_bd + b_sm_off,                                            \
                       wT + (size_t)(_s * BK + b_kk) * G4 + bcol_off);            \
            cp_commit();                                                          \
        } while (0)

        ISSUE(0);
        ISSUE(1);

        for (int s = 0; s < NSTAGE; s++) {
            if (s + 1 < NSTAGE) cp_wait1(); else cp_wait0();
            __syncthreads();
            if (s + 2 < NSTAGE) ISSUE(s + 2);

            const float* A  = sA + (s % 3) * (BK * 64) + g * 4 * 64 + tr * 8;
            const float* Bm = sB + (s % 3) * (BK * 64) + g * 4 * 64 + tc * 8;
#pragma unroll
            for (int kk = 0; kk < 4; kk++) {
                const float* ap = A + kk * 64;
                u64 a0 = *(const u64*)(ap + 0);   // rows +0,+1
                u64 a1 = *(const u64*)(ap + 2);   // rows +2,+3
                u64 a2 = *(const u64*)(ap + 4);   // rows +4,+5
                u64 a3 = *(const u64*)(ap + 6);   // rows +6,+7
                const float* bp = Bm + kk * 64;
                {   // cols 0..3
                    float4 b4 = *(const float4*)(bp);
                    u64 b0 = rep2(b4.x), b1 = rep2(b4.y), b2 = rep2(b4.z), b3 = rep2(b4.w);
                    fma2(acc[0][0], a0, b0); fma2(acc[0][1], a0, b1); fma2(acc[0][2], a0, b2); fma2(acc[0][3], a0, b3);
                    fma2(acc[1][0], a1, b0); fma2(acc[1][1], a1, b1); fma2(acc[1][2], a1, b2); fma2(acc[1][3], a1, b3);
                    fma2(acc[2][0], a2, b0); fma2(acc[2][1], a2, b1); fma2(acc[2][2], a2, b2); fma2(acc[2][3], a2, b3);
                    fma2(acc[3][0], a3, b0); fma2(acc[3][1], a3, b1); fma2(acc[3][2], a3, b2); fma2(acc[3][3], a3, b3);
                }
                {   // cols 4..7
                    float4 b4 = *(const float4*)(bp + 4);
                    u64 b0 = rep2(b4.x), b1 = rep2(b4.y), b2 = rep2(b4.z), b3 = rep2(b4.w);
                    fma2(acc[0][4], a0, b0); fma2(acc[0][5], a0, b1); fma2(acc[0][6], a0, b2); fma2(acc[0][7], a0, b3);
                    fma2(acc[1][4], a1, b0); fma2(acc[1][5], a1, b1); fma2(acc[1][6], a1, b2); fma2(acc[1][7], a1, b3);
                    fma2(acc[2][4], a2, b0); fma2(acc[2][5], a2, b1); fma2(acc[2][6], a2, b2); fma2(acc[2][7], a2, b3);
                    fma2(acc[3][4], a3, b0); fma2(acc[3][5], a3, b1); fma2(acc[3][6], a3, b2); fma2(acc[3][7], a3, b3);
                }
            }
        }
#undef ISSUE

        // RACE FIX: all warps finish reading the last ring buffers before the
        // sG alias (regions overlap the ring) is written.
        __syncthreads();

        // ---- write this group's partials into region g ----
        {
            float* dst = sG + g * SG_REGION + tc * 8;
#pragma unroll
            for (int i = 0; i < 8; i++) {
                int m = tr * 8 + i;
                int p = i >> 1;
                float4 v0, v1;
                if (i & 1) {
                    v0 = make_float4(hi32(acc[p][0]), hi32(acc[p][1]), hi32(acc[p][2]), hi32(acc[p][3]));
                    v1 = make_float4(hi32(acc[p][4]), hi32(acc[p][5]), hi32(acc[p][6]), hi32(acc[p][7]));
                } else {
                    v0 = make_float4(lo32(acc[p][0]), lo32(acc[p][1]), lo32(acc[p][2]), lo32(acc[p][3]));
                    v1 = make_float4(lo32(acc[p][4]), lo32(acc[p][5]), lo32(acc[p][6]), lo32(acc[p][7]));
                }
                *(float4*)(dst + m * SG_STRIDE)     = v0;
                *(float4*)(dst + m * SG_STRIDE + 4) = v1;
            }
        }
        __syncthreads();

        // ---- activation: sum 8 partials per gate + xp ----
        const float* xp = g_xp + ((size_t)dir * T_ + t) * B_ * G4;
#pragma unroll
        for (int r = 0; r < 2; r++) {
            int p4 = tid + r * NTHR;
            int b = p4 >> 4, j = p4 & 15;
            int jc = jt * 16 + j;
            const int base = b * SG_STRIDE;
            const float* xpb = xp + (size_t)b * G4 + jt * 16 + j;

            float ig = xpb[0 * H_], fg = xpb[1 * H_], gg = xpb[2 * H_], og = xpb[3 * H_];
#pragma unroll
            for (int q = 0; q < 8; q++) {
                const float* rgn = sG + q * SG_REGION + base;
                ig += rgn[     j];
                fg += rgn[16 + j];
                gg += rgn[32 + j];
                og += rgn[48 + j];
            }

            float si = 1.0f / (1.0f + __expf(-ig));
            float sf = 1.0f / (1.0f + __expf(-fg));
            float so = 1.0f / (1.0f + __expf(-og));
            float cn = sf * creg[r] + si * tanhf(gg);
            float hn = so * tanhf(cn);
            creg[r] = cn;

            hTn[jc * B_ + b] = hn;
            out[((size_t)b * T_ + t) * (2 * H_) + dir * H_ + jc] = hn;

            if (t == T_ - 1) {
                const size_t base2 = (size_t)B_ * T_ * 2 * H_;
                out[base2 + (dir ? 2 : 0) * (size_t)BH + b * H_ + jc] = hn;
                out[base2 + (dir ? 3 : 1) * (size_t)BH + b * H_ + jc] = cn;
            }
        }

        // ---- grid barrier ----
        __threadfence();
        __syncthreads();
        if (tid == 0) {
            unsigned ticket = atomicAdd(&g_bar_count, 1u);
            if (ticket == NCTA - 1) {
                g_bar_count = 0;
                __threadfence();
                g_bar_sense = (unsigned)(t + 1);
            } else {
                while (g_bar_sense < (unsigned)(t + 1)) { __nanosleep(32); }
            }
        }
        __syncthreads();
    }
}

// ---------------------------------------------------------------------------
// Launch
// ---------------------------------------------------------------------------
extern "C" void kernel_launch(void* const* d_in, const int* in_sizes, int n_in,
                              void* d_out, int out_size) {
    (void)in_sizes; (void)n_in; (void)out_size;
    const float* x       = (const float*)d_in[0];
    const float* w_ih_fw = (const float*)d_in[1];
    const float* w_hh_fw = (const float*)d_in[2];
    const float* b_ih_fw = (const float*)d_in[3];
    const float* b_hh_fw = (const float*)d_in[4];
    const float* w_ih_bw = (const float*)d_in[5];
    const float* w_hh_bw = (const float*)d_in[6];
    const float* b_ih_bw = (const float*)d_in[7];
    const float* b_hh_bw = (const float*)d_in[8];
    float* out = (float*)d_out;

    cudaFuncSetAttribute(lstm_persistent_kernel,
                         cudaFuncAttributeMaxDynamicSharedMemorySize, SMEM_BYTES);

    init_state_kernel<<<(2 * BH + 255) / 256, 256>>>();

    dim3 gtw(G4 / 32, H_ / 32, 2);
    transpose_w_kernel<<<gtw, 256>>>(w_hh_fw, w_hh_bw);

    dim3 gproj(64, T_, 2);
    input_proj_kernel<<<gproj, 128>>>(x, w_ih_fw, w_ih_bw,
                                      b_ih_fw, b_hh_fw, b_ih_bw, b_hh_bw);

    lstm_persistent_kernel<<<NCTA, NTHR, SMEM_BYTES>>>(out);
}